// round 3
// baseline (speedup 1.0000x reference)
#include <cuda_runtime.h>
#include <math.h>

typedef unsigned long long u64;

#define B_      32
#define CIN     128
#define COUT    128
#define HW      128
#define ZD      512
#define EPSV    1e-8f

// ---------------- scratch (device globals; no allocation allowed) ----------------
__device__ float g_mod[B_ * CIN];      // (style+1)
__device__ float g_S[COUT * CIN];      // sum_k weight^2
__device__ float g_dscale[B_ * COUT];  // demod factor

// ---------------- helpers ----------------
__device__ __forceinline__ u64 pack2(float lo, float hi) {
    u64 r;
    asm("mov.b64 %0, {%1, %2};" : "=l"(r) : "f"(lo), "f"(hi));
    return r;
}
__device__ __forceinline__ void fma2(u64& d, u64 a, u64 b) {
    asm("fma.rn.f32x2 %0, %1, %2, %0;" : "+l"(d) : "l"(a), "l"(b));
}
__device__ __forceinline__ float2 unpack2(u64 v) {
    float2 r;
    asm("mov.b64 {%0, %1}, %2;" : "=f"(r.x), "=f"(r.y) : "l"(v));
    return r;
}
__device__ __forceinline__ float mishf(float v) {
    // v * tanh(softplus(v)); large-v safe: expf->inf, log1pf->inf, tanhf->1
    return v * tanhf(log1pf(expf(v)));
}

// ---------------- kernel 1: style = z @ W_style^T + b ; g_mod = style + 1 ----------------
__global__ void style_kernel(const float* __restrict__ z,
                             const float* __restrict__ Wsty,
                             const float* __restrict__ bsty) {
    int b = blockIdx.x;     // 0..31
    int i = threadIdx.x;    // 0..127
    __shared__ float zs[ZD];
    for (int k = threadIdx.x; k < ZD; k += blockDim.x) zs[k] = z[b * ZD + k];
    __syncthreads();
    float s = bsty[i];
    const float* wr = Wsty + i * ZD;
    #pragma unroll 4
    for (int k = 0; k < ZD; k++) s += zs[k] * wr[k];
    g_mod[b * CIN + i] = s + 1.0f;
}

// ---------------- kernel 2: S[o][i] = sum_k w[o][i][k]^2 ----------------
__global__ void ssum_kernel(const float* __restrict__ w) {
    int o = blockIdx.x;     // 0..127
    int i = threadIdx.x;    // 0..127
    const float* p = w + (o * CIN + i) * 9;
    float s = 0.f;
    #pragma unroll
    for (int k = 0; k < 9; k++) s += p[k] * p[k];
    g_S[o * CIN + i] = s;
}

// ---------------- kernel 3: dscale[b][o] = rsqrt(sum_i mod^2 * S + eps) ----------------
__global__ void dscale_kernel() {
    int b = blockIdx.x;     // 0..31
    int o = threadIdx.x;    // 0..127
    const float* m = g_mod + b * CIN;
    const float* s = g_S + o * CIN;
    float acc = 0.f;
    #pragma unroll 4
    for (int i = 0; i < CIN; i++) {
        float mv = m[i];
        acc += mv * mv * s[i];
    }
    g_dscale[b * COUT + o] = rsqrtf(acc + EPSV);
}

// ---------------- kernel 4: conv (shared weight) + demod scale + mish ----------------
// block: 256 threads. tile: 64 oc x 16x16 px, one batch.
// thread: oc_sub = t&15 -> 4 consecutive oc; row = t>>4 -> 16 cols of that row.
#define ICC 8
#define XS_BYTES  (ICC * 18 * 22 * 4)           // 12672
#define WS_BYTES  (ICC * 9 * 68 * 4)            // 19584
#define SM_BYTES  (XS_BYTES + WS_BYTES + 64)    // + mods

__global__ void __launch_bounds__(256, 2)
conv_kernel(const float* __restrict__ x,
            const float* __restrict__ weight,
            float* __restrict__ out) {
    __shared__ __align__(16) unsigned char sm[SM_BYTES];
    float (*xs)[18][22] = reinterpret_cast<float (*)[18][22]>(sm);
    float (*ws)[9][68]  = reinterpret_cast<float (*)[9][68]>(sm + XS_BYTES);
    float* mods         = reinterpret_cast<float*>(sm + XS_BYTES + WS_BYTES);
    float (*obuf)[16][17] = reinterpret_cast<float (*)[16][17]>(sm);  // epilogue reuse (16*16*17*4 = 17408 < 32256)

    const int t      = threadIdx.x;
    const int oc_sub = t & 15;
    const int row    = t >> 4;

    const int b   = blockIdx.z >> 1;
    const int ocb = (blockIdx.z & 1) * 64;
    const int ty0 = blockIdx.y * 16;
    const int tx0 = blockIdx.x * 16;

    u64 acc[4][8];
    #pragma unroll
    for (int j = 0; j < 4; j++)
        #pragma unroll
        for (int i = 0; i < 8; i++) acc[j][i] = 0ull;

    const float* xbatch = x + (size_t)b * CIN * HW * HW;

    for (int cb = 0; cb < CIN / ICC; cb++) {
        __syncthreads();
        // mods for this ic chunk
        if (t < ICC) mods[t] = g_mod[b * CIN + cb * ICC + t];
        // x tile with halo: ICC * 18 * 18 = 2592 elems
        for (int i = t; i < ICC * 18 * 18; i += 256) {
            int ic = i / 324;
            int r  = (i % 324) / 18;
            int c  = i % 18;
            int gy = ty0 + r - 1;
            int gx = tx0 + c - 1;
            float v = 0.f;
            if (gy >= 0 && gy < HW && gx >= 0 && gx < HW)
                v = xbatch[(size_t)(cb * ICC + ic) * (HW * HW) + gy * HW + gx];
            xs[ic][r][c] = v;  // modulation folded below at consume? fold here:
        }
        __syncthreads();
        // fold modulation (need mods visible; do in a second tiny pass to avoid
        // ordering issues between mods write and xs writes by different threads)
        for (int i = t; i < ICC * 18 * 18; i += 256) {
            int ic = i / 324;
            xs[ic][i % 324 / 18][i % 18] *= mods[ic];
        }
        // weights: ICC*9*64 = 4608 logical elems, coalesced global reads
        for (int i = t; i < ICC * 9 * 64; i += 256) {
            int oc = i / 72;
            int j  = i % 72;
            int ic = j / 9;
            int k  = j % 9;
            ws[ic][k][oc] = weight[(size_t)(ocb + oc) * (CIN * 9) + (cb * ICC + ic) * 9 + k];
        }
        __syncthreads();

        for (int ic = 0; ic < ICC; ic++) {
            #pragma unroll
            for (int ky = 0; ky < 3; ky++) {
                const float* xr = &xs[ic][row + ky][0];
                float f[18];
                #pragma unroll
                for (int c = 0; c < 18; c++) f[c] = xr[c];
                u64 xe[9], xo[8];
                #pragma unroll
                for (int i = 0; i < 9; i++) xe[i] = pack2(f[2 * i], f[2 * i + 1]);
                #pragma unroll
                for (int i = 0; i < 8; i++) xo[i] = pack2(f[2 * i + 1], f[2 * i + 2]);
                #pragma unroll
                for (int kx = 0; kx < 3; kx++) {
                    const float4 wv = *reinterpret_cast<const float4*>(&ws[ic][ky * 3 + kx][oc_sub * 4]);
                    u64 w0 = pack2(wv.x, wv.x);
                    u64 w1 = pack2(wv.y, wv.y);
                    u64 w2 = pack2(wv.z, wv.z);
                    u64 w3 = pack2(wv.w, wv.w);
                    const u64* xp = (kx == 0) ? xe : (kx == 1) ? xo : (xe + 1);
                    #pragma unroll
                    for (int i = 0; i < 8; i++) {
                        fma2(acc[0][i], xp[i], w0);
                        fma2(acc[1][i], xp[i], w1);
                        fma2(acc[2][i], xp[i], w2);
                        fma2(acc[3][i], xp[i], w3);
                    }
                }
            }
        }
    }

    // epilogue: 4 passes through smem for coalesced stores
    for (int p = 0; p < 4; p++) {
        __syncthreads();
        #pragma unroll
        for (int i = 0; i < 8; i++) {
            float2 v = unpack2(acc[p][i]);
            obuf[oc_sub][row][2 * i]     = v.x;
            obuf[oc_sub][row][2 * i + 1] = v.y;
        }
        __syncthreads();
        #pragma unroll
        for (int k = 0; k < 16; k++) {
            int e     = t + k * 256;
            int oc_s  = e >> 8;
            int row_r = (e >> 4) & 15;
            int c     = e & 15;
            int oc    = ocb + oc_s * 4 + p;
            float dsc = g_dscale[b * COUT + oc];
            float v   = obuf[oc_s][row_r][c] * dsc;
            out[((size_t)(b * COUT + oc) * HW + (ty0 + row_r)) * HW + (tx0 + c)] = mishf(v);
        }
    }
}

// ---------------- launch ----------------
extern "C" void kernel_launch(void* const* d_in, const int* in_sizes, int n_in,
                              void* d_out, int out_size) {
    const float* x    = (const float*)d_in[0];
    const float* z    = (const float*)d_in[1];
    const float* w    = (const float*)d_in[2];
    const float* Wsty = (const float*)d_in[3];
    const float* bsty = (const float*)d_in[4];
    float* out = (float*)d_out;

    style_kernel<<<B_, CIN>>>(z, Wsty, bsty);
    ssum_kernel<<<COUT, CIN>>>(w);
    dscale_kernel<<<B_, COUT>>>();
    conv_kernel<<<dim3(HW / 16, HW / 16, B_ * 2), 256>>>(x, w, out);
}

// round 4
// speedup vs baseline: 1.0000x; 1.0000x over previous
#include <cuda_runtime.h>
#include <math.h>

typedef unsigned long long u64;

#define B_      32
#define CIN     128
#define COUT    128
#define HW      128
#define ZD      512
#define EPSV    1e-8f

// ---------------- scratch (device globals; no allocation allowed) ----------------
__device__ float g_mod[B_ * CIN];      // (style+1)
__device__ float g_S[COUT * CIN];      // sum_k weight^2
__device__ float g_dscale[B_ * COUT];  // demod factor

// ---------------- helpers ----------------
__device__ __forceinline__ u64 pack2(float lo, float hi) {
    u64 r;
    asm("mov.b64 %0, {%1, %2};" : "=l"(r) : "f"(lo), "f"(hi));
    return r;
}
__device__ __forceinline__ void fma2(u64& d, u64 a, u64 b) {
    asm("fma.rn.f32x2 %0, %1, %2, %0;" : "+l"(d) : "l"(a), "l"(b));
}
__device__ __forceinline__ float2 unpack2(u64 v) {
    float2 r;
    asm("mov.b64 {%0, %1}, %2;" : "=f"(r.x), "=f"(r.y) : "l"(v));
    return r;
}
__device__ __forceinline__ float mishf(float v) {
    // v * tanh(softplus(v)); large-v safe: expf->inf, log1pf->inf, tanhf->1
    return v * tanhf(log1pf(expf(v)));
}

// ---------------- kernel 1: style = z @ W_style^T + b ; g_mod = style + 1 ----------------
__global__ void style_kernel(const float* __restrict__ z,
                             const float* __restrict__ Wsty,
                             const float* __restrict__ bsty) {
    int b = blockIdx.x;     // 0..31
    int i = threadIdx.x;    // 0..127
    __shared__ float zs[ZD];
    for (int k = threadIdx.x; k < ZD; k += blockDim.x) zs[k] = z[b * ZD + k];
    __syncthreads();
    float s = bsty[i];
    const float* wr = Wsty + i * ZD;
    #pragma unroll 4
    for (int k = 0; k < ZD; k++) s += zs[k] * wr[k];
    g_mod[b * CIN + i] = s + 1.0f;
}

// ---------------- kernel 2: S[o][i] = sum_k w[o][i][k]^2 ----------------
__global__ void ssum_kernel(const float* __restrict__ w) {
    int o = blockIdx.x;     // 0..127
    int i = threadIdx.x;    // 0..127
    const float* p = w + (o * CIN + i) * 9;
    float s = 0.f;
    #pragma unroll
    for (int k = 0; k < 9; k++) s += p[k] * p[k];
    g_S[o * CIN + i] = s;
}

// ---------------- kernel 3: dscale[b][o] = rsqrt(sum_i mod^2 * S + eps) ----------------
__global__ void dscale_kernel() {
    int b = blockIdx.x;     // 0..31
    int o = threadIdx.x;    // 0..127
    const float* m = g_mod + b * CIN;
    const float* s = g_S + o * CIN;
    float acc = 0.f;
    #pragma unroll 4
    for (int i = 0; i < CIN; i++) {
        float mv = m[i];
        acc += mv * mv * s[i];
    }
    g_dscale[b * COUT + o] = rsqrtf(acc + EPSV);
}

// ---------------- kernel 4: conv (shared weight) + demod scale + mish ----------------
// block: 256 threads. tile: 64 oc x 16x16 px, one batch.
// thread: oc_sub = t&15 -> 4 consecutive oc; row = t>>4 -> 16 cols of that row.
#define ICC 8
#define XS_BYTES  (ICC * 18 * 22 * 4)           // 12672
#define WS_BYTES  (ICC * 9 * 68 * 4)            // 19584
#define SM_BYTES  (XS_BYTES + WS_BYTES + 64)    // + mods

__global__ void __launch_bounds__(256, 2)
conv_kernel(const float* __restrict__ x,
            const float* __restrict__ weight,
            float* __restrict__ out) {
    __shared__ __align__(16) unsigned char sm[SM_BYTES];
    float (*xs)[18][22] = reinterpret_cast<float (*)[18][22]>(sm);
    float (*ws)[9][68]  = reinterpret_cast<float (*)[9][68]>(sm + XS_BYTES);
    float* mods         = reinterpret_cast<float*>(sm + XS_BYTES + WS_BYTES);
    float (*obuf)[16][17] = reinterpret_cast<float (*)[16][17]>(sm);  // epilogue reuse (16*16*17*4 = 17408 < 32256)

    const int t      = threadIdx.x;
    const int oc_sub = t & 15;
    const int row    = t >> 4;

    const int b   = blockIdx.z >> 1;
    const int ocb = (blockIdx.z & 1) * 64;
    const int ty0 = blockIdx.y * 16;
    const int tx0 = blockIdx.x * 16;

    u64 acc[4][8];
    #pragma unroll
    for (int j = 0; j < 4; j++)
        #pragma unroll
        for (int i = 0; i < 8; i++) acc[j][i] = 0ull;

    const float* xbatch = x + (size_t)b * CIN * HW * HW;

    for (int cb = 0; cb < CIN / ICC; cb++) {
        __syncthreads();
        // mods for this ic chunk
        if (t < ICC) mods[t] = g_mod[b * CIN + cb * ICC + t];
        // x tile with halo: ICC * 18 * 18 = 2592 elems
        for (int i = t; i < ICC * 18 * 18; i += 256) {
            int ic = i / 324;
            int r  = (i % 324) / 18;
            int c  = i % 18;
            int gy = ty0 + r - 1;
            int gx = tx0 + c - 1;
            float v = 0.f;
            if (gy >= 0 && gy < HW && gx >= 0 && gx < HW)
                v = xbatch[(size_t)(cb * ICC + ic) * (HW * HW) + gy * HW + gx];
            xs[ic][r][c] = v;  // modulation folded below at consume? fold here:
        }
        __syncthreads();
        // fold modulation (need mods visible; do in a second tiny pass to avoid
        // ordering issues between mods write and xs writes by different threads)
        for (int i = t; i < ICC * 18 * 18; i += 256) {
            int ic = i / 324;
            xs[ic][i % 324 / 18][i % 18] *= mods[ic];
        }
        // weights: ICC*9*64 = 4608 logical elems, coalesced global reads
        for (int i = t; i < ICC * 9 * 64; i += 256) {
            int oc = i / 72;
            int j  = i % 72;
            int ic = j / 9;
            int k  = j % 9;
            ws[ic][k][oc] = weight[(size_t)(ocb + oc) * (CIN * 9) + (cb * ICC + ic) * 9 + k];
        }
        __syncthreads();

        for (int ic = 0; ic < ICC; ic++) {
            #pragma unroll
            for (int ky = 0; ky < 3; ky++) {
                const float* xr = &xs[ic][row + ky][0];
                float f[18];
                #pragma unroll
                for (int c = 0; c < 18; c++) f[c] = xr[c];
                u64 xe[9], xo[8];
                #pragma unroll
                for (int i = 0; i < 9; i++) xe[i] = pack2(f[2 * i], f[2 * i + 1]);
                #pragma unroll
                for (int i = 0; i < 8; i++) xo[i] = pack2(f[2 * i + 1], f[2 * i + 2]);
                #pragma unroll
                for (int kx = 0; kx < 3; kx++) {
                    const float4 wv = *reinterpret_cast<const float4*>(&ws[ic][ky * 3 + kx][oc_sub * 4]);
                    u64 w0 = pack2(wv.x, wv.x);
                    u64 w1 = pack2(wv.y, wv.y);
                    u64 w2 = pack2(wv.z, wv.z);
                    u64 w3 = pack2(wv.w, wv.w);
                    const u64* xp = (kx == 0) ? xe : (kx == 1) ? xo : (xe + 1);
                    #pragma unroll
                    for (int i = 0; i < 8; i++) {
                        fma2(acc[0][i], xp[i], w0);
                        fma2(acc[1][i], xp[i], w1);
                        fma2(acc[2][i], xp[i], w2);
                        fma2(acc[3][i], xp[i], w3);
                    }
                }
            }
        }
    }

    // epilogue: 4 passes through smem for coalesced stores
    for (int p = 0; p < 4; p++) {
        __syncthreads();
        #pragma unroll
        for (int i = 0; i < 8; i++) {
            float2 v = unpack2(acc[p][i]);
            obuf[oc_sub][row][2 * i]     = v.x;
            obuf[oc_sub][row][2 * i + 1] = v.y;
        }
        __syncthreads();
        #pragma unroll
        for (int k = 0; k < 16; k++) {
            int e     = t + k * 256;
            int oc_s  = e >> 8;
            int row_r = (e >> 4) & 15;
            int c     = e & 15;
            int oc    = ocb + oc_s * 4 + p;
            float dsc = g_dscale[b * COUT + oc];
            float v   = obuf[oc_s][row_r][c] * dsc;
            out[((size_t)(b * COUT + oc) * HW + (ty0 + row_r)) * HW + (tx0 + c)] = mishf(v);
        }
    }
}

// ---------------- launch ----------------
extern "C" void kernel_launch(void* const* d_in, const int* in_sizes, int n_in,
                              void* d_out, int out_size) {
    const float* x    = (const float*)d_in[0];
    const float* z    = (const float*)d_in[1];
    const float* w    = (const float*)d_in[2];
    const float* Wsty = (const float*)d_in[3];
    const float* bsty = (const float*)d_in[4];
    float* out = (float*)d_out;

    style_kernel<<<B_, CIN>>>(z, Wsty, bsty);
    ssum_kernel<<<COUT, CIN>>>(w);
    dscale_kernel<<<B_, COUT>>>();
    conv_kernel<<<dim3(HW / 16, HW / 16, B_ * 2), 256>>>(x, w, out);
}

// round 8
// speedup vs baseline: 3.8320x; 3.8319x over previous
#include <cuda_runtime.h>
#include <cuda_bf16.h>
#include <math.h>
#include <stdint.h>

#define B_      32
#define CIN     128
#define COUT    128
#define HW      128
#define ZD      512
#define EPSV    1e-8f

// ---------------- device scratch ----------------
__device__ float g_mod[B_ * CIN];
__device__ float g_S[COUT * CIN];
__device__ float g_dscale[B_ * COUT];
// weights bf16 hi/lo: [st = tap*2+ihalf][oc][64]
__device__ __align__(256) __nv_bfloat16 g_wh[18 * 128 * 64];
__device__ __align__(256) __nv_bfloat16 g_wl[18 * 128 * 64];
// x*mod bf16 hi/lo, NHWC: [b][y][x][ic]
__device__ __align__(256) __nv_bfloat16 g_xh[(size_t)B_ * HW * HW * CIN];
__device__ __align__(256) __nv_bfloat16 g_xl[(size_t)B_ * HW * HW * CIN];

// ---------------- helpers ----------------
__device__ __forceinline__ uint32_t smem_u32(const void* p) {
    uint32_t a;
    asm("{ .reg .u64 t; cvta.to.shared.u64 t, %1; cvt.u32.u64 %0, t; }" : "=r"(a) : "l"(p));
    return a;
}
__device__ __forceinline__ void cpasync16(uint32_t dst, const void* src, int sz) {
    asm volatile("cp.async.cg.shared.global [%0], [%1], 16, %2;"
        :: "r"(dst), "l"(src), "r"(sz) : "memory");
}
#define CP_COMMIT() asm volatile("cp.async.commit_group;" ::: "memory")
#define CP_WAIT1()  asm volatile("cp.async.wait_group 1;" ::: "memory")
#define CP_WAIT0()  asm volatile("cp.async.wait_group 0;" ::: "memory")

__device__ __forceinline__ void ldsm_x4(uint32_t a[4], uint32_t addr) {
    asm volatile("ldmatrix.sync.aligned.m8n8.x4.shared.b16 {%0,%1,%2,%3}, [%4];"
        : "=r"(a[0]), "=r"(a[1]), "=r"(a[2]), "=r"(a[3]) : "r"(addr));
}
__device__ __forceinline__ void ldsm_x2(uint32_t b[2], uint32_t addr) {
    asm volatile("ldmatrix.sync.aligned.m8n8.x2.shared.b16 {%0,%1}, [%2];"
        : "=r"(b[0]), "=r"(b[1]) : "r"(addr));
}
__device__ __forceinline__ void mma16816(float d[4], const uint32_t a[4], const uint32_t b[2]) {
    asm volatile("mma.sync.aligned.m16n8k16.row.col.f32.bf16.bf16.f32 "
        "{%0,%1,%2,%3}, {%4,%5,%6,%7}, {%8,%9}, {%0,%1,%2,%3};"
        : "+f"(d[0]), "+f"(d[1]), "+f"(d[2]), "+f"(d[3])
        : "r"(a[0]), "r"(a[1]), "r"(a[2]), "r"(a[3]), "r"(b[0]), "r"(b[1]));
}
__device__ __forceinline__ float mishf(float v) {
    return v * tanhf(log1pf(expf(v)));
}

// ---------------- pre-kernels ----------------
__global__ void style_kernel(const float* __restrict__ z,
                             const float* __restrict__ Wsty,
                             const float* __restrict__ bsty) {
    int b = blockIdx.x, i = threadIdx.x;
    __shared__ float zs[ZD];
    for (int k = threadIdx.x; k < ZD; k += blockDim.x) zs[k] = z[b * ZD + k];
    __syncthreads();
    float s = bsty[i];
    const float* wr = Wsty + i * ZD;
    #pragma unroll 4
    for (int k = 0; k < ZD; k++) s += zs[k] * wr[k];
    g_mod[b * CIN + i] = s + 1.0f;
}

__global__ void ssum_kernel(const float* __restrict__ w) {
    int o = blockIdx.x, i = threadIdx.x;
    const float* p = w + (o * CIN + i) * 9;
    float s = 0.f;
    #pragma unroll
    for (int k = 0; k < 9; k++) s += p[k] * p[k];
    g_S[o * CIN + i] = s;
}

__global__ void dscale_kernel() {
    int b = blockIdx.x, o = threadIdx.x;
    const float* m = g_mod + b * CIN;
    const float* s = g_S + o * CIN;
    float acc = 0.f;
    #pragma unroll 4
    for (int i = 0; i < CIN; i++) { float mv = m[i]; acc += mv * mv * s[i]; }
    g_dscale[b * COUT + o] = rsqrtf(acc + EPSV);
}

__global__ void wcvt_kernel(const float* __restrict__ w) {
    int idx = blockIdx.x * 512 + threadIdx.x;      // 0..147455
    int j   = idx & 63;
    int oc  = (idx >> 6) & 127;
    int st  = idx >> 13;
    int ih  = st & 1;
    int tap = st >> 1;
    float v = w[(oc * CIN + (ih * 64 + j)) * 9 + tap];
    __nv_bfloat16 h = __float2bfloat16(v);
    g_wh[idx] = h;
    g_wl[idx] = __float2bfloat16(v - __bfloat162float(h));
}

__global__ void xcvt_kernel(const float* __restrict__ x) {
    extern __shared__ float sm[];   // 128 * 133
    int b = blockIdx.x >> 7;
    int y = blockIdx.x & 127;
    #pragma unroll
    for (int i = 0; i < 16; i++) {
        int idx4 = i * 256 + threadIdx.x;          // 0..4095
        int ic = idx4 >> 5;
        int x4 = (idx4 & 31) * 4;
        float4 v = *(const float4*)(x + (((size_t)(b * CIN + ic)) * HW + y) * HW + x4);
        float m = g_mod[b * CIN + ic];
        float* d = sm + ic * 133 + x4;
        d[0] = v.x * m; d[1] = v.y * m; d[2] = v.z * m; d[3] = v.w * m;
    }
    __syncthreads();
    int xc = threadIdx.x >> 1;
    int ih = threadIdx.x & 1;
    size_t o = (((size_t)(b * HW + y)) * HW + xc) * CIN + ih * 64;
    uint32_t* oh = (uint32_t*)(g_xh + o);
    uint32_t* ol = (uint32_t*)(g_xl + o);
    #pragma unroll
    for (int q = 0; q < 32; q++) {
        float v0 = sm[(ih * 64 + 2 * q) * 133 + xc];
        float v1 = sm[(ih * 64 + 2 * q + 1) * 133 + xc];
        uint32_t ph;
        asm("cvt.rn.bf16x2.f32 %0, %1, %2;" : "=r"(ph) : "f"(v1), "f"(v0));
        float h0 = __uint_as_float(ph << 16);
        float h1 = __uint_as_float(ph & 0xFFFF0000u);
        uint32_t pl;
        float l0 = v0 - h0, l1 = v1 - h1;
        asm("cvt.rn.bf16x2.f32 %0, %1, %2;" : "=r"(pl) : "f"(l1), "f"(l0));
        oh[q] = ph;
        ol[q] = pl;
    }
}

// ---------------- main conv: mma.sync implicit GEMM ----------------
// CTA = (b, image row y0). D[128 oc x 128 px], K = 18 stages of 64.
// smem stage: AH/AL 16KB each, BH/BL 16KB each; double buffered = 128KB.
#define STAGE_B  65536
#define OFF_AH   0
#define OFF_AL   16384
#define OFF_BH   32768
#define OFF_BL   49152
#define SM_TOTAL 131072
#define SWZ(row, cb) ((cb) ^ (((row) & 7) << 4))

__global__ void __launch_bounds__(256, 1)
conv_mma_kernel(float* __restrict__ out) {
    extern __shared__ __align__(1024) unsigned char smem[];
    const uint32_t sb = smem_u32(smem);
    const int t   = threadIdx.x;
    const int wid = t >> 5;
    const int lid = t & 31;
    const int b   = blockIdx.x >> 7;
    const int y0  = blockIdx.x & 127;

    const int wm = wid & 3;          // oc block (32)
    const int wn = wid >> 2;         // px block (64)
    const int oc0 = wm * 32;
    const int n0  = wn * 64;

    float d[2][8][4];
    #pragma unroll
    for (int mi = 0; mi < 2; mi++)
        #pragma unroll
        for (int ni = 0; ni < 8; ni++)
            #pragma unroll
            for (int j = 0; j < 4; j++) d[mi][ni][j] = 0.f;

    // ---- stage issue lambda-ish (macro via function) ----
    auto issue_stage = [&](int s, int buf) {
        const int tap = s >> 1;
        const int ih  = s & 1;
        const int ky  = tap / 3;
        const int kx  = tap - ky * 3;
        const uint32_t bb = sb + (uint32_t)buf * STAGE_B;
        // A: 2048 x 16B
        #pragma unroll
        for (int i = 0; i < 8; i++) {
            int idx = i * 256 + t;
            int hl  = idx >> 10;
            int r   = idx & 1023;
            int oc  = r >> 3, c = r & 7;
            const __nv_bfloat16* src = (hl ? g_wl : g_wh) + (size_t)s * 8192 + oc * 64 + c * 8;
            cpasync16(bb + (hl ? OFF_AL : OFF_AH) + oc * 128 + SWZ(oc, c * 16), src, 16);
        }
        // B: 2048 x 16B (halo zfill)
        const int yi = y0 + ky - 1;
        const bool yok = (unsigned)yi < (unsigned)HW;
        #pragma unroll
        for (int i = 0; i < 8; i++) {
            int idx = i * 256 + t;
            int hl  = idx >> 10;
            int r   = idx & 1023;
            int px  = r >> 3, c = r & 7;
            int xi  = px + kx - 1;
            bool ok = yok && (unsigned)xi < (unsigned)HW;
            const __nv_bfloat16* src = (hl ? g_xl : g_xh)
                + (((size_t)(b * HW + (ok ? yi : 0))) * HW + (ok ? xi : 0)) * CIN + ih * 64 + c * 8;
            cpasync16(bb + (hl ? OFF_BL : OFF_BH) + px * 128 + SWZ(px, c * 16), src, ok ? 16 : 0);
        }
    };

    issue_stage(0, 0);
    CP_COMMIT();

    for (int s = 0; s < 18; s++) {
        const int buf = s & 1;
        if (s + 1 < 18) {
            issue_stage(s + 1, buf ^ 1);
            CP_COMMIT();
            CP_WAIT1();
        } else {
            CP_WAIT0();
        }
        __syncthreads();

        const uint32_t bb = sb + (uint32_t)buf * STAGE_B;
        #pragma unroll
        for (int k16 = 0; k16 < 4; k16++) {
            // A fragments (hi, lo) for 2 m-tiles
            uint32_t ah[2][4], al[2][4];
            {
                const uint32_t acb = (uint32_t)k16 * 32 + ((lid >> 4) & 1) * 16;
                #pragma unroll
                for (int mi = 0; mi < 2; mi++) {
                    uint32_t row = oc0 + mi * 16 + (lid & 7) + ((lid >> 3) & 1) * 8;
                    uint32_t off = row * 128 + SWZ(row, acb);
                    ldsm_x4(ah[mi], bb + OFF_AH + off);
                    ldsm_x4(al[mi], bb + OFF_AL + off);
                }
            }
            // B tiles
            const uint32_t bcb = (uint32_t)k16 * 32 + ((lid >> 3) & 1) * 16;
            #pragma unroll
            for (int ni = 0; ni < 8; ni++) {
                uint32_t brow = n0 + ni * 8 + (lid & 7);
                uint32_t boff = brow * 128 + SWZ(brow, bcb);
                uint32_t bh[2], bl[2];
                ldsm_x2(bh, bb + OFF_BH + boff);
                ldsm_x2(bl, bb + OFF_BL + boff);
                #pragma unroll
                for (int mi = 0; mi < 2; mi++) {
                    mma16816(d[mi][ni], ah[mi], bh);
                    mma16816(d[mi][ni], ah[mi], bl);
                    mma16816(d[mi][ni], al[mi], bh);
                }
            }
        }
        __syncthreads();
    }

    // ---- epilogue: dscale * mish, transpose through smem, coalesced out ----
    float* ep = (float*)smem;        // [128 px][132]
    float dsc[2][2];
    #pragma unroll
    for (int mi = 0; mi < 2; mi++) {
        dsc[mi][0] = g_dscale[b * COUT + oc0 + mi * 16 + (lid >> 2)];
        dsc[mi][1] = g_dscale[b * COUT + oc0 + mi * 16 + (lid >> 2) + 8];
    }
    #pragma unroll
    for (int mi = 0; mi < 2; mi++) {
        #pragma unroll
        for (int ni = 0; ni < 8; ni++) {
            #pragma unroll
            for (int j = 0; j < 4; j++) {
                int oc = oc0 + mi * 16 + (lid >> 2) + ((j >> 1) ? 8 : 0);
                int px = n0 + ni * 8 + (lid & 3) * 2 + (j & 1);
                ep[px * 132 + oc] = mishf(d[mi][ni][j] * dsc[mi][(j >> 1)]);
            }
        }
    }
    __syncthreads();

    const int oc2  = t & 127;
    const int half = t >> 7;
    float* dst = out + (((size_t)(b * COUT + oc2)) * HW + y0) * HW + half * 64;
    #pragma unroll
    for (int g = 0; g < 16; g++) {
        int px = half * 64 + g * 4;
        float4 v;
        v.x = ep[(px + 0) * 132 + oc2];
        v.y = ep[(px + 1) * 132 + oc2];
        v.z = ep[(px + 2) * 132 + oc2];
        v.w = ep[(px + 3) * 132 + oc2];
        *(float4*)(dst + g * 4) = v;
    }
}

// ---------------- launch ----------------
extern "C" void kernel_launch(void* const* d_in, const int* in_sizes, int n_in,
                              void* d_out, int out_size) {
    const float* x    = (const float*)d_in[0];
    const float* z    = (const float*)d_in[1];
    const float* w    = (const float*)d_in[2];
    const float* Wsty = (const float*)d_in[3];
    const float* bsty = (const float*)d_in[4];
    float* out = (float*)d_out;

    cudaFuncSetAttribute(conv_mma_kernel, cudaFuncAttributeMaxDynamicSharedMemorySize, SM_TOTAL);
    cudaFuncSetAttribute(xcvt_kernel, cudaFuncAttributeMaxDynamicSharedMemorySize, 128 * 133 * 4);

    style_kernel<<<B_, CIN>>>(z, Wsty, bsty);
    ssum_kernel<<<COUT, CIN>>>(w);
    dscale_kernel<<<B_, COUT>>>();
    wcvt_kernel<<<288, 512>>>(w);
    xcvt_kernel<<<B_ * HW, 256, 128 * 133 * 4>>>(x);
    conv_mma_kernel<<<B_ * HW, 256, SM_TOTAL>>>(out);
}